// round 15
// baseline (speedup 1.0000x reference)
#include <cuda_runtime.h>

// ---------------- problem constants ----------------
#define NND   50000
#define DEG   16
#define IN_F  128
#define HID   64
#define NH    4
#define BATCH 64

#define NT1   128                 // targets = [uid(64), iid(64)]
#define NS1   (NT1*DEG + NT1)     // 2176 local nodes needing h1

typedef unsigned long long ull;

// ---------------- scratch ----------------
__device__ float g_wvec1[1024];        // wl1[4][128] | wr1[4][128]
__device__ float g_wvec2[512];         // wl2[256] | wr2[256]
__device__ float g_Z[NH*NS1*IN_F];     // head-major: [h][v][128]
__device__ float g_h1[NS1*NH*HID];     // [2176][256]
__device__ float g_h2[NT1*HID];        // [128][64]
__device__ int   g_flag;               // prep-done flag   (reset by K_B)
__device__ int   g_cnt1;               // gemm-done count  (reset by K_A)
__device__ int   g_cnt2;               // layer2 ticket    (reset by K_A)

// ---------------- helpers ----------------
__device__ __forceinline__ ull pack_dup(float x) {
    ull r; asm("mov.b64 %0, {%1, %1};" : "=l"(r) : "f"(x)); return r;
}
__device__ __forceinline__ void ffma2(ull& acc, ull a, ull b) {
    asm("fma.rn.f32x2 %0, %1, %2, %0;" : "+l"(acc) : "l"(a), "l"(b));
}
__device__ __forceinline__ float2 unpack2(ull v) {
    float2 f; asm("mov.b64 {%0, %1}, %2;" : "=f"(f.x), "=f"(f.y) : "l"(v)); return f;
}
__device__ __forceinline__ float dot4(float4 a, float4 b) {
    return a.x*b.x + a.y*b.y + a.z*b.z + a.w*b.w;
}

// ============== K_A: prep (blocks 0-5) + flag + layer-1 ======================
__global__ __launch_bounds__(128)
void ka_kernel(const int* __restrict__ src, const int* __restrict__ feat_ids,
               const int* __restrict__ uid, const int* __restrict__ iid,
               const float* __restrict__ emb,
               const float* __restrict__ W1, const float* __restrict__ al1,
               const float* __restrict__ ar1,
               const float* __restrict__ W2, const float* __restrict__ al2,
               const float* __restrict__ ar2,
               float* __restrict__ Z) {
    const int v   = blockIdx.x;
    const int tid = threadIdx.x, lane = tid & 31, w = tid >> 5;

    if (v == 0 && tid == 0) { g_cnt1 = 0; g_cnt2 = 0; }   // reset K_B counters

    // ---- phase 0: prep (blocks 0..5 compute 256 wvec entries each) ----
    if (v < 6) {
        #pragma unroll
        for (int r = 0; r < 2; r++) {
            int id = v*256 + r*128 + tid;   // 0..1535
            float s = 0.f;
            if (id < 1024) {
                int h = (id >> 7) & 3, k = id & 127;
                const float* av   = ((id >= 512) ? ar1 : al1) + h*HID;
                const float* wrow = W1 + (long)k*(NH*HID) + h*HID;
                #pragma unroll
                for (int q = 0; q < 16; q++)
                    s += dot4(*(const float4*)(av + 4*q), *(const float4*)(wrow + 4*q));
                g_wvec1[id] = s;
            } else {
                int id2 = id - 1024;
                int k = id2 & 255;
                const float* av   = (id2 < 256) ? al2 : ar2;
                const float* wrow = W2 + (long)k*HID;
                #pragma unroll
                for (int q = 0; q < 16; q++)
                    s += dot4(*(const float4*)(av + 4*q), *(const float4*)(wrow + 4*q));
                g_wvec2[id2] = s;
            }
        }
        __threadfence();
        __syncthreads();
        if (tid == 0) atomicAdd(&g_flag, 1);
    }
    // ---- spin until prep done (flag reset to 0 by prior K_B -> safe) ----
    if (tid == 0) {
        while (*(volatile int*)&g_flag < 6) __nanosleep(20);
    }
    __syncthreads();
    __threadfence();

    // ---- phase 1: layer-1 attention + input-space aggregation ----
    __shared__ float rows[17*132];
    __shared__ float wv[8*128];
    __shared__ int   fids[17];

    int u;
    if (v < NT1*DEG) {
        int x = v >> 4;
        int t = (x < BATCH) ? uid[x] : iid[x - BATCH];
        u = src[t*DEG + (v & 15)];
    } else {
        int x = v - NT1*DEG;
        u = (x < BATCH) ? uid[x] : iid[x - BATCH];
    }
    if (tid < 16)       fids[tid] = feat_ids[src[u*DEG + tid]];
    else if (tid == 16) fids[16]  = feat_ids[u];
    __syncthreads();

    for (int idx = tid; idx < 17*32; idx += 128) {
        int r = idx >> 5, q = idx & 31;
        *(float4*)(rows + r*132 + q*4) =
            *(const float4*)(emb + (long)fids[r]*IN_F + q*4);
    }
    for (int idx = tid; idx < 256; idx += 128)
        *(float4*)(wv + idx*4) = *(const float4*)(g_wvec1 + idx*4);
    __syncthreads();

    const int h = w;                 // warp per head
    float acc = 0.f;
    {
        const float* wp = (lane < 16) ? (wv + h*128) : (wv + 512 + h*128);
        const float* rp = rows + (lane < 17 ? lane : 0)*132;
        if (lane < 17) {
            #pragma unroll
            for (int q = 0; q < 32; q++)
                acc += dot4(*(const float4*)(rp + 4*q), *(const float4*)(wp + 4*q));
        }
    }
    float er = __shfl_sync(~0u, acc, 16);
    float e  = acc + er;
    e = e > 0.f ? e : 0.2f * e;      // leaky_relu(0.2)
    float m = e;
    #pragma unroll
    for (int o = 8; o > 0; o >>= 1) m = fmaxf(m, __shfl_xor_sync(~0u, m, o, 16));
    float ex = __expf(e - m);
    float s = ex;
    #pragma unroll
    for (int o = 8; o > 0; o >>= 1) s += __shfl_xor_sync(~0u, s, o, 16);
    float alpha = ex / s;

    float4 z = make_float4(0.f, 0.f, 0.f, 0.f);
    #pragma unroll
    for (int e2 = 0; e2 < 16; e2++) {
        float a = __shfl_sync(~0u, alpha, e2);
        float4 rv = *(const float4*)(rows + e2*132 + lane*4);
        z.x += a*rv.x; z.y += a*rv.y; z.z += a*rv.z; z.w += a*rv.w;
    }
    *(float4*)(Z + ((long)h*NS1 + v)*IN_F + lane*4) = z;
}

// ====== K_B: gemm1b (all 544) + spin + layer-2 (blocks 0-127) + score ========
__global__ __launch_bounds__(256)
void kb_kernel(const float* __restrict__ Z, const float* __restrict__ W1,
               const float* __restrict__ b1, const float* __restrict__ W2,
               const float* __restrict__ b2,
               float* __restrict__ h1, float* __restrict__ h2,
               float* __restrict__ out) {
    __shared__ float smA[128*18];    // Zs [k][16+pad]   / later: wv2
    __shared__ float smB[128*68];    // Ws [k][64+pad]   / later: h1 rows
    __shared__ float dots_sm[17];
    __shared__ float alpha_sm[16];
    __shared__ float z2[256];
    __shared__ float part[4][64];
    __shared__ float sloss[BATCH];
    __shared__ int   ticket_sm;
    const int tid = threadIdx.x, lane = tid & 31, w = tid >> 5;

    if (blockIdx.x == 0 && tid == 0) g_flag = 0;   // reset K_A flag for next replay

    // ---- phase A: h1 tile = relu(Z[h] @ W1slice + b1) ----
    const int t = blockIdx.x >> 2, h = blockIdx.x & 3;
    const float* Zt = Z + ((long)h*NS1 + t*16)*IN_F;
    for (int idx = tid; idx < 512; idx += 256) {          // 16x128 floats as float4
        int r = idx >> 5, q = idx & 31;
        float4 vv = ((const float4*)Zt)[r*32 + q];
        smA[(q*4+0)*18 + r] = vv.x;
        smA[(q*4+1)*18 + r] = vv.y;
        smA[(q*4+2)*18 + r] = vv.z;
        smA[(q*4+3)*18 + r] = vv.w;
    }
    for (int idx = tid; idx < 2048; idx += 256) {         // 128x64 floats as float4
        int k = idx >> 4, q = idx & 15;
        float4 vv = *(const float4*)(W1 + (long)k*(NH*HID) + h*HID + q*4);
        *(float4*)(&smB[k*68 + q*4]) = vv;
    }
    __syncthreads();

    {
        const int c = tid & 31, rp = tid >> 5;            // col, row-pair
        ull acc0 = 0ull, acc1 = 0ull;                     // cols c and c+32
        #pragma unroll 8
        for (int k = 0; k < 128; k++) {
            ull a2 = *(const ull*)(&smA[k*18 + rp*2]);
            ull b0 = pack_dup(smB[k*68 + c]);
            ull bb = pack_dup(smB[k*68 + c + 32]);
            ffma2(acc0, a2, b0);
            ffma2(acc1, a2, bb);
        }
        float2 p0 = unpack2(acc0);
        float2 p1 = unpack2(acc1);
        int v0 = t*16 + rp*2;
        float bc0 = b1[h*HID + c], bc1 = b1[h*HID + c + 32];
        h1[(long)v0*(NH*HID)     + h*HID + c]      = fmaxf(p0.x + bc0, 0.f);
        h1[(long)(v0+1)*(NH*HID) + h*HID + c]      = fmaxf(p0.y + bc0, 0.f);
        h1[(long)v0*(NH*HID)     + h*HID + c + 32] = fmaxf(p1.x + bc1, 0.f);
        h1[(long)(v0+1)*(NH*HID) + h*HID + c + 32] = fmaxf(p1.y + bc1, 0.f);
    }
    __threadfence();
    __syncthreads();
    if (tid == 0) atomicAdd(&g_cnt1, 1);

    if (blockIdx.x >= NT1) return;       // only blocks 0..127 continue

    // ---- spin until all 544 gemm tiles done ----
    if (tid == 0) {
        while (*(volatile int*)&g_cnt1 < 544) __nanosleep(20);
    }
    __syncthreads();
    __threadfence();

    // ---- phase B: layer-2 attention + agg + GEMM2 + bias ----
    const int i = blockIdx.x;
    float* rows = smB;                   // 17 x 260 floats (4420 <= 8704)
    float* wv   = smA;                   // 512 floats
    for (int idx = tid; idx < 17*16; idx += 256) {
        int r = idx >> 4, q = idx & 15;
        int grow = (r < 16) ? (i*DEG + r) : (NT1*DEG + i);
        *(float4*)(rows + r*260 + q*16) =
            *(const float4*)(h1 + (long)grow*(NH*HID) + q*16);
        *(float4*)(rows + r*260 + q*16 + 4) =
            *(const float4*)(h1 + (long)grow*(NH*HID) + q*16 + 4);
        *(float4*)(rows + r*260 + q*16 + 8) =
            *(const float4*)(h1 + (long)grow*(NH*HID) + q*16 + 8);
        *(float4*)(rows + r*260 + q*16 + 12) =
            *(const float4*)(h1 + (long)grow*(NH*HID) + q*16 + 12);
    }
    for (int idx = tid; idx < 128; idx += 256)
        *(float4*)(wv + idx*4) = *(const float4*)(g_wvec2 + idx*4);
    __syncthreads();

    for (int d = w; d < 17; d += 8) {
        const float* wp = ((d < 16) ? wv : (wv + 256)) + lane*8;
        const float* rp = rows + d*260 + lane*8;
        float p = dot4(*(const float4*)rp,     *(const float4*)wp)
                + dot4(*(const float4*)(rp+4), *(const float4*)(wp+4));
        #pragma unroll
        for (int o = 16; o; o >>= 1) p += __shfl_xor_sync(~0u, p, o);
        if (lane == 0) dots_sm[d] = p;
    }
    __syncthreads();

    if (w == 0 && lane < 16) {
        float e = dots_sm[lane] + dots_sm[16];
        e = e > 0.f ? e : 0.2f * e;
        float m = e;
        #pragma unroll
        for (int o = 8; o > 0; o >>= 1) m = fmaxf(m, __shfl_xor_sync(0xFFFFu, m, o, 16));
        float ex = __expf(e - m);
        float s = ex;
        #pragma unroll
        for (int o = 8; o > 0; o >>= 1) s += __shfl_xor_sync(0xFFFFu, s, o, 16);
        alpha_sm[lane] = ex / s;
    }
    __syncthreads();

    float za = 0.f, zb = 0.f;
    #pragma unroll
    for (int e = 0; e < 16; e += 2) {
        za += alpha_sm[e]   * rows[e*260 + tid];
        zb += alpha_sm[e+1] * rows[(e+1)*260 + tid];
    }
    z2[tid] = za + zb;
    __syncthreads();

    const int n = tid & 63, kh = tid >> 6;
    float a0=0.f, a1=0.f, a2=0.f, a3=0.f;
    #pragma unroll
    for (int k = 0; k < 64; k += 4) {
        a0 += z2[kh*64+k]   * W2[(long)(kh*64+k)*HID + n];
        a1 += z2[kh*64+k+1] * W2[(long)(kh*64+k+1)*HID + n];
        a2 += z2[kh*64+k+2] * W2[(long)(kh*64+k+2)*HID + n];
        a3 += z2[kh*64+k+3] * W2[(long)(kh*64+k+3)*HID + n];
    }
    part[kh][n] = (a0 + a1) + (a2 + a3);
    __syncthreads();
    if (tid < 64)
        h2[(long)i*HID + tid] =
            part[0][tid] + part[1][tid] + part[2][tid] + part[3][tid] + b2[tid];

    // ---- phase C: last ticket-holder emits scores/labels/loss ----
    __threadfence();
    __syncthreads();
    if (tid == 0) ticket_sm = atomicAdd(&g_cnt2, 1);
    __syncthreads();
    if (ticket_sm != NT1 - 1) return;
    __threadfence();

    for (int r = 0; r < 8; r++) {
        int row = w*8 + r;
        float su0 = h2[row*HID + lane];
        float su1 = h2[row*HID + lane + 32];
        float si0 = h2[(BATCH + row)*HID + lane];
        float si1 = h2[(BATCH + row)*HID + lane + 32];
        float sc0 = su0*si0, sc1 = su1*si1;
        out[1 + row*BATCH + lane]      = sc0;
        out[1 + row*BATCH + lane + 32] = sc1;
        out[1 + BATCH*BATCH + row*BATCH + lane]      = (row == lane)      ? 1.f : 0.f;
        out[1 + BATCH*BATCH + row*BATCH + lane + 32] = (row == lane + 32) ? 1.f : 0.f;
        float diag = (row < 32) ? __shfl_sync(~0u, sc0, row)
                                : __shfl_sync(~0u, sc1, row - 32);
        float m = fmaxf(sc0, sc1);
        #pragma unroll
        for (int o = 16; o; o >>= 1) m = fmaxf(m, __shfl_xor_sync(~0u, m, o));
        float s = expf(sc0 - m) + expf(sc1 - m);
        #pragma unroll
        for (int o = 16; o; o >>= 1) s += __shfl_xor_sync(~0u, s, o);
        if (lane == 0) sloss[row] = m + logf(s) - diag;
    }
    __syncthreads();
    if (w == 0) {
        float s = sloss[lane] + sloss[lane + 32];
        #pragma unroll
        for (int o = 16; o; o >>= 1) s += __shfl_xor_sync(~0u, s, o);
        if (lane == 0) out[0] = s / (float)BATCH;
    }
}

// ---------------- launcher ----------------
extern "C" void kernel_launch(void* const* d_in, const int* in_sizes, int n_in,
                              void* d_out, int out_size) {
    const int*   feat_ids = (const int*)  d_in[0];
    const int*   src      = (const int*)  d_in[1];
    const int*   user_ids = (const int*)  d_in[3];
    const int*   item_ids = (const int*)  d_in[4];
    const float* emb      = (const float*)d_in[5];
    const float* W1       = (const float*)d_in[6];
    const float* a_l1     = (const float*)d_in[7];
    const float* a_r1     = (const float*)d_in[8];
    const float* b1       = (const float*)d_in[9];
    const float* W2       = (const float*)d_in[10];
    const float* a_l2     = (const float*)d_in[11];
    const float* a_r2     = (const float*)d_in[12];
    const float* b2       = (const float*)d_in[13];
    float* out = (float*)d_out;

    float *Z, *h1, *h2;
    cudaGetSymbolAddress((void**)&Z,  g_Z);
    cudaGetSymbolAddress((void**)&h1, g_h1);
    cudaGetSymbolAddress((void**)&h2, g_h2);

    ka_kernel<<<NS1, 128>>>(src, feat_ids, user_ids, item_ids, emb,
                            W1, a_l1, a_r1, W2, a_l2, a_r2, Z);
    kb_kernel<<<544, 256>>>(Z, W1, b1, W2, b2, h1, h2, out);
}

// round 16
// speedup vs baseline: 1.1526x; 1.1526x over previous
#include <cuda_runtime.h>

// ---------------- problem constants ----------------
#define NND   50000
#define DEG   16
#define IN_F  128
#define HID   64
#define NH    4
#define BATCH 64

#define NT1   128                 // targets = [uid(64), iid(64)]
#define NS1   (NT1*DEG + NT1)     // 2176 local nodes needing h1

typedef unsigned long long ull;

// ---------------- scratch ----------------
__device__ float g_wvec1[1024];        // wl1[4][128] | wr1[4][128]
__device__ float g_wvec2[512];         // wl2[256] | wr2[256]
__device__ float g_Z[NH*NS1*IN_F];     // head-major: [h][v][128]
__device__ float g_h1[NS1*NH*HID];     // [2176][256]
__device__ float g_h2[NT1*HID];        // [128][64]
__device__ int   g_cnt1;               // gemm tiles done (reset by prep)
__device__ int   g_cnt2;               // layer2 ticket   (reset by prep)

// ---------------- helpers ----------------
__device__ __forceinline__ ull pack_dup(float x) {
    ull r; asm("mov.b64 %0, {%1, %1};" : "=l"(r) : "f"(x)); return r;
}
__device__ __forceinline__ void ffma2(ull& acc, ull a, ull b) {
    asm("fma.rn.f32x2 %0, %1, %2, %0;" : "+l"(acc) : "l"(a), "l"(b));
}
__device__ __forceinline__ float2 unpack2(ull v) {
    float2 f; asm("mov.b64 {%0, %1}, %2;" : "=f"(f.x), "=f"(f.y) : "l"(v)); return f;
}
__device__ __forceinline__ float dot4(float4 a, float4 b) {
    return a.x*b.x + a.y*b.y + a.z*b.z + a.w*b.w;
}

// ---------------- K1: attention projection vectors (6 blocks) ----------------
__global__ void prep_kernel(const float* __restrict__ W1, const float* __restrict__ al1,
                            const float* __restrict__ ar1, const float* __restrict__ W2,
                            const float* __restrict__ al2, const float* __restrict__ ar2) {
    int id = blockIdx.x*256 + threadIdx.x;     // 0..1535
    if (id == 0) { g_cnt1 = 0; g_cnt2 = 0; }   // reset fused-kernel counters
    if (id < 1024) {
        int h = (id >> 7) & 3, k = id & 127;
        const float* av   = ((id >= 512) ? ar1 : al1) + h*HID;
        const float* wrow = W1 + (long)k*(NH*HID) + h*HID;
        float s = 0.f;
        #pragma unroll
        for (int q = 0; q < 16; q++)
            s += dot4(*(const float4*)(av + 4*q), *(const float4*)(wrow + 4*q));
        g_wvec1[id] = s;
    } else {
        int id2 = id - 1024;
        int k = id2 & 255;
        const float* av   = (id2 < 256) ? al2 : ar2;
        const float* wrow = W2 + (long)k*HID;
        float s = 0.f;
        #pragma unroll
        for (int q = 0; q < 16; q++)
            s += dot4(*(const float4*)(av + 4*q), *(const float4*)(wrow + 4*q));
        g_wvec2[id2] = s;
    }
}

// ---------------- K2: layer-1 attention + input-space aggregation ------------
__global__ __launch_bounds__(128)
void layer1_kernel(const int* __restrict__ src, const int* __restrict__ feat_ids,
                   const int* __restrict__ uid, const int* __restrict__ iid,
                   const float* __restrict__ emb, float* __restrict__ Z) {
    __shared__ float rows[17*132];
    __shared__ float wv[8*128];
    __shared__ int   fids[17];
    const int v = blockIdx.x;
    const int tid = threadIdx.x, lane = tid & 31, w = tid >> 5;

    int u;
    if (v < NT1*DEG) {
        int x = v >> 4;
        int t = (x < BATCH) ? uid[x] : iid[x - BATCH];
        u = src[t*DEG + (v & 15)];
    } else {
        int x = v - NT1*DEG;
        u = (x < BATCH) ? uid[x] : iid[x - BATCH];
    }
    if (tid < 16)       fids[tid] = feat_ids[src[u*DEG + tid]];
    else if (tid == 16) fids[16]  = feat_ids[u];
    __syncthreads();

    for (int idx = tid; idx < 17*32; idx += 128) {
        int r = idx >> 5, q = idx & 31;
        *(float4*)(rows + r*132 + q*4) =
            *(const float4*)(emb + (long)fids[r]*IN_F + q*4);
    }
    for (int idx = tid; idx < 256; idx += 128)
        *(float4*)(wv + idx*4) = *(const float4*)(g_wvec1 + idx*4);
    __syncthreads();

    const int h = w;
    float acc = 0.f;
    {
        const float* wp = (lane < 16) ? (wv + h*128) : (wv + 512 + h*128);
        const float* rp = rows + (lane < 17 ? lane : 0)*132;
        if (lane < 17) {
            #pragma unroll
            for (int q = 0; q < 32; q++)
                acc += dot4(*(const float4*)(rp + 4*q), *(const float4*)(wp + 4*q));
        }
    }
    float er = __shfl_sync(~0u, acc, 16);
    float e  = acc + er;
    e = e > 0.f ? e : 0.2f * e;
    float m = e;
    #pragma unroll
    for (int o = 8; o > 0; o >>= 1) m = fmaxf(m, __shfl_xor_sync(~0u, m, o, 16));
    float ex = __expf(e - m);
    float s = ex;
    #pragma unroll
    for (int o = 8; o > 0; o >>= 1) s += __shfl_xor_sync(~0u, s, o, 16);
    float alpha = ex / s;

    float4 z = make_float4(0.f, 0.f, 0.f, 0.f);
    #pragma unroll
    for (int e2 = 0; e2 < 16; e2++) {
        float a = __shfl_sync(~0u, alpha, e2);
        float4 rv = *(const float4*)(rows + e2*132 + lane*4);
        z.x += a*rv.x; z.y += a*rv.y; z.z += a*rv.z; z.w += a*rv.w;
    }
    *(float4*)(Z + ((long)h*NS1 + v)*IN_F + lane*4) = z;
}

// ====== K3: gemm1b (136 blocks, R14 tiling) + spin + layer2 + score ==========
__global__ __launch_bounds__(256)
void kbc_kernel(const float* __restrict__ Z, const float* __restrict__ W1,
                const float* __restrict__ b1, const float* __restrict__ W2,
                const float* __restrict__ b2,
                float* __restrict__ h1, float* __restrict__ h2,
                float* __restrict__ out) {
    __shared__ float pool[64*66 + 64*64];   // Zs | Ws, reused in phase B
    __shared__ float dots_sm[17];
    __shared__ float alpha_sm[16];
    __shared__ float z2s[256];
    __shared__ float part[4][64];
    __shared__ float sloss[BATCH];
    __shared__ int   ticket_sm;
    float* Zs = pool;                 // [k][66]
    float* Ws = pool + 64*66;         // [k][64]
    const int tid = threadIdx.x, lane = tid & 31, w = tid >> 5;

    // ---- phase A: 64x64 h1 tile (same tiling as R14 gemm1b) ----
    {
        const int m0 = (blockIdx.x >> 2) * 64;
        const int h  = blockIdx.x & 3;
        const int wr = w & 3, wc = w >> 2;
        const int lr = lane >> 3, lc = lane & 7;
        const int rbase = wr*16 + lr*4;
        const int cbase = wc*32 + lc*4;
        const float* Zh = Z + (long)h*NS1*IN_F;

        ull acc2[2][4];
        #pragma unroll
        for (int i = 0; i < 2; i++)
            #pragma unroll
            for (int j = 0; j < 4; j++) acc2[i][j] = 0ull;

        for (int k0 = 0; k0 < IN_F; k0 += 64) {
            for (int idx = tid; idx < 1024; idx += 256) {
                int r = idx >> 4, q = idx & 15;
                float4 vv = *(const float4*)(Zh + (long)(m0 + r)*IN_F + k0 + q*4);
                Zs[(q*4+0)*66 + r] = vv.x; Zs[(q*4+1)*66 + r] = vv.y;
                Zs[(q*4+2)*66 + r] = vv.z; Zs[(q*4+3)*66 + r] = vv.w;
            }
            for (int idx = tid; idx < 1024; idx += 256) {
                int k = idx >> 4, q = idx & 15;
                *(float4*)(&Ws[k*64 + q*4]) =
                    *(const float4*)(W1 + (long)(k0 + k)*(NH*HID) + h*HID + q*4);
            }
            __syncthreads();
            #pragma unroll 16
            for (int k = 0; k < 64; k++) {
                ull a0 = *(const ull*)(&Zs[k*66 + rbase]);
                ull a1 = *(const ull*)(&Zs[k*66 + rbase + 2]);
                float4 b4 = *(const float4*)(&Ws[k*64 + cbase]);
                ull b0 = pack_dup(b4.x), bb1 = pack_dup(b4.y);
                ull b2v = pack_dup(b4.z), b3 = pack_dup(b4.w);
                ffma2(acc2[0][0], a0, b0); ffma2(acc2[0][1], a0, bb1);
                ffma2(acc2[0][2], a0, b2v); ffma2(acc2[0][3], a0, b3);
                ffma2(acc2[1][0], a1, b0); ffma2(acc2[1][1], a1, bb1);
                ffma2(acc2[1][2], a1, b2v); ffma2(acc2[1][3], a1, b3);
            }
            __syncthreads();
        }

        float4 bv = *(const float4*)(b1 + h*HID + cbase);
        #pragma unroll
        for (int p = 0; p < 2; p++) {
            float2 c0 = unpack2(acc2[p][0]);
            float2 c1 = unpack2(acc2[p][1]);
            float2 c2 = unpack2(acc2[p][2]);
            float2 c3 = unpack2(acc2[p][3]);
            int r0 = m0 + rbase + 2*p;
            float4 o0 = make_float4(fmaxf(c0.x + bv.x, 0.f), fmaxf(c1.x + bv.y, 0.f),
                                    fmaxf(c2.x + bv.z, 0.f), fmaxf(c3.x + bv.w, 0.f));
            float4 o1 = make_float4(fmaxf(c0.y + bv.x, 0.f), fmaxf(c1.y + bv.y, 0.f),
                                    fmaxf(c2.y + bv.z, 0.f), fmaxf(c3.y + bv.w, 0.f));
            *(float4*)(h1 + (long)r0*(NH*HID) + h*HID + cbase)       = o0;
            *(float4*)(h1 + (long)(r0 + 1)*(NH*HID) + h*HID + cbase) = o1;
        }
    }
    __threadfence();
    __syncthreads();
    if (tid == 0) atomicAdd(&g_cnt1, 1);

    if (blockIdx.x >= NT1) return;       // blocks 128..135 done

    // ---- spin until all 136 gemm tiles done (all blocks co-resident) ----
    if (tid == 0) {
        while (*(volatile int*)&g_cnt1 < 136) __nanosleep(20);
    }
    __syncthreads();
    __threadfence();

    // ---- phase B: layer-2 attention + agg + GEMM2 + bias ----
    const int i = blockIdx.x;
    float* rows = pool;                  // 17*260 = 4420 floats
    float* wv   = pool + 4480;           // 512 floats (8320 total pool)
    for (int idx = tid; idx < 17*64; idx += 256) {
        int r = idx >> 6, q = idx & 63;
        int grow = (r < 16) ? (i*DEG + r) : (NT1*DEG + i);
        *(float4*)(rows + r*260 + q*4) =
            *(const float4*)(h1 + (long)grow*(NH*HID) + q*4);
    }
    for (int idx = tid; idx < 128; idx += 256)
        *(float4*)(wv + idx*4) = *(const float4*)(g_wvec2 + idx*4);
    __syncthreads();

    for (int d = w; d < 17; d += 8) {
        const float* wp = ((d < 16) ? wv : (wv + 256)) + lane*8;
        const float* rp = rows + d*260 + lane*8;
        float p = dot4(*(const float4*)rp,     *(const float4*)wp)
                + dot4(*(const float4*)(rp+4), *(const float4*)(wp+4));
        #pragma unroll
        for (int o = 16; o; o >>= 1) p += __shfl_xor_sync(~0u, p, o);
        if (lane == 0) dots_sm[d] = p;
    }
    __syncthreads();

    if (w == 0 && lane < 16) {
        float e = dots_sm[lane] + dots_sm[16];
        e = e > 0.f ? e : 0.2f * e;
        float m = e;
        #pragma unroll
        for (int o = 8; o > 0; o >>= 1) m = fmaxf(m, __shfl_xor_sync(0xFFFFu, m, o, 16));
        float ex = __expf(e - m);
        float s = ex;
        #pragma unroll
        for (int o = 8; o > 0; o >>= 1) s += __shfl_xor_sync(0xFFFFu, s, o, 16);
        alpha_sm[lane] = ex / s;
    }
    __syncthreads();

    float za = 0.f, zb = 0.f;
    #pragma unroll
    for (int e = 0; e < 16; e += 2) {
        za += alpha_sm[e]   * rows[e*260 + tid];
        zb += alpha_sm[e+1] * rows[(e+1)*260 + tid];
    }
    z2s[tid] = za + zb;
    __syncthreads();

    const int n = tid & 63, kh = tid >> 6;
    float a0=0.f, a1=0.f, a2=0.f, a3=0.f;
    #pragma unroll
    for (int k = 0; k < 64; k += 4) {
        a0 += z2s[kh*64+k]   * W2[(long)(kh*64+k)*HID + n];
        a1 += z2s[kh*64+k+1] * W2[(long)(kh*64+k+1)*HID + n];
        a2 += z2s[kh*64+k+2] * W2[(long)(kh*64+k+2)*HID + n];
        a3 += z2s[kh*64+k+3] * W2[(long)(kh*64+k+3)*HID + n];
    }
    part[kh][n] = (a0 + a1) + (a2 + a3);
    __syncthreads();
    if (tid < 64)
        h2[(long)i*HID + tid] =
            part[0][tid] + part[1][tid] + part[2][tid] + part[3][tid] + b2[tid];

    // ---- phase C: last ticket-holder emits scores/labels/loss ----
    __threadfence();
    __syncthreads();
    if (tid == 0) ticket_sm = atomicAdd(&g_cnt2, 1);
    __syncthreads();
    if (ticket_sm != NT1 - 1) return;
    __threadfence();

    for (int r = 0; r < 8; r++) {
        int row = w*8 + r;
        float su0 = h2[row*HID + lane];
        float su1 = h2[row*HID + lane + 32];
        float si0 = h2[(BATCH + row)*HID + lane];
        float si1 = h2[(BATCH + row)*HID + lane + 32];
        float sc0 = su0*si0, sc1 = su1*si1;
        out[1 + row*BATCH + lane]      = sc0;
        out[1 + row*BATCH + lane + 32] = sc1;
        out[1 + BATCH*BATCH + row*BATCH + lane]      = (row == lane)      ? 1.f : 0.f;
        out[1 + BATCH*BATCH + row*BATCH + lane + 32] = (row == lane + 32) ? 1.f : 0.f;
        float diag = (row < 32) ? __shfl_sync(~0u, sc0, row)
                                : __shfl_sync(~0u, sc1, row - 32);
        float m = fmaxf(sc0, sc1);
        #pragma unroll
        for (int o = 16; o; o >>= 1) m = fmaxf(m, __shfl_xor_sync(~0u, m, o));
        float s = expf(sc0 - m) + expf(sc1 - m);
        #pragma unroll
        for (int o = 16; o; o >>= 1) s += __shfl_xor_sync(~0u, s, o);
        if (lane == 0) sloss[row] = m + logf(s) - diag;
    }
    __syncthreads();
    if (w == 0) {
        float s = sloss[lane] + sloss[lane + 32];
        #pragma unroll
        for (int o = 16; o; o >>= 1) s += __shfl_xor_sync(~0u, s, o);
        if (lane == 0) out[0] = s / (float)BATCH;
    }
}

// ---------------- launcher ----------------
extern "C" void kernel_launch(void* const* d_in, const int* in_sizes, int n_in,
                              void* d_out, int out_size) {
    const int*   feat_ids = (const int*)  d_in[0];
    const int*   src      = (const int*)  d_in[1];
    const int*   user_ids = (const int*)  d_in[3];
    const int*   item_ids = (const int*)  d_in[4];
    const float* emb      = (const float*)d_in[5];
    const float* W1       = (const float*)d_in[6];
    const float* a_l1     = (const float*)d_in[7];
    const float* a_r1     = (const float*)d_in[8];
    const float* b1       = (const float*)d_in[9];
    const float* W2       = (const float*)d_in[10];
    const float* a_l2     = (const float*)d_in[11];
    const float* a_r2     = (const float*)d_in[12];
    const float* b2       = (const float*)d_in[13];
    float* out = (float*)d_out;

    float *Z, *h1, *h2;
    cudaGetSymbolAddress((void**)&Z,  g_Z);
    cudaGetSymbolAddress((void**)&h1, g_h1);
    cudaGetSymbolAddress((void**)&h2, g_h2);

    prep_kernel<<<6, 256>>>(W1, a_l1, a_r1, W2, a_l2, a_r2);
    layer1_kernel<<<NS1, 128>>>(src, feat_ids, user_ids, item_ids, emb, Z);
    kbc_kernel<<<136, 256>>>(Z, W1, b1, W2, b2, h1, h2, out);
}